// round 14
// baseline (speedup 1.0000x reference)
#include <cuda_runtime.h>
#include <cstdint>
#include <math.h>

#define BB   8
#define TT   2048
#define EE   512
#define HH   8
#define HD   64
#define NQH  4
#define NLAY 2
#define NQF  8
#define FFND 2048
#define BTN  (BB*TT)
#define NQKV 1152              // 512 q + 512 k + 32 v_compact + 96 pad

#define NSTAGE 3
#define KTILE  32

// ---- scratch (static device globals; no allocation allowed) ----
static __device__ float d_xr  [(size_t)BTN*EE];
static __device__ float d_wqkv[(size_t)NQKV*EE];
static __device__ float d_qkv [(size_t)BTN*NQKV];
static __device__ float d_vTc [(size_t)BB*32*TT];
static __device__ float d_o   [(size_t)BTN*32];
static __device__ float d_q32 [(size_t)BTN*32];
static __device__ float d_woc [(size_t)EE*32];
static __device__ float d_att [(size_t)BTN*EE];
static __device__ float d_x1  [(size_t)BTN*EE];
static __device__ float d_f8  [(size_t)BTN*32];
static __device__ float d_w1p [(size_t)FFND*32];
static __device__ float d_w2r [(size_t)EE*FFND];
static __device__ float d_f   [(size_t)BTN*EE];
static __device__ float g_attA[32], g_attB[32], g_ffnA[8], g_ffnB[8];

// ============================ helpers =======================================
__device__ __forceinline__ uint32_t smem_u32(const void* p) {
    uint32_t a;
    asm("{ .reg .u64 t; cvta.to.shared.u64 t, %1; cvt.u32.u64 %0, t; }" : "=r"(a) : "l"(p));
    return a;
}
__device__ __forceinline__ float f2tf(float x) {       // round-to-nearest tf32, as float bits
    uint32_t u;
    asm("cvt.rna.tf32.f32 %0, %1;" : "=r"(u) : "f"(x));
    return __uint_as_float(u);
}
__device__ __forceinline__ void mma8(float* d,
    float a0, float a1, float a2, float a3, float b0, float b1)
{
    asm volatile(
        "mma.sync.aligned.m16n8k8.row.col.f32.tf32.tf32.f32 "
        "{%0,%1,%2,%3}, {%4,%5,%6,%7}, {%8,%9}, {%0,%1,%2,%3};"
        : "+f"(d[0]), "+f"(d[1]), "+f"(d[2]), "+f"(d[3])
        : "r"(__float_as_uint(a0)), "r"(__float_as_uint(a1)),
          "r"(__float_as_uint(a2)), "r"(__float_as_uint(a3)),
          "r"(__float_as_uint(b0)), "r"(__float_as_uint(b1)));
}
#define CPA16(dst, src) \
    asm volatile("cp.async.cg.shared.global [%0], [%1], 16;" :: "r"(dst), "l"(src) : "memory")
#define CPA_COMMIT() asm volatile("cp.async.commit_group;" ::: "memory")
#define CPA_WAIT1()  asm volatile("cp.async.wait_group 1;" ::: "memory")
#define CPA_WAIT0()  asm volatile("cp.async.wait_group 0;" ::: "memory")

// ============================================================================
// Generic tf32 mma.sync NT GEMM (used for QKV and wo): C = act(alpha*A*B^T)
// CTA 128x128, 8 warps (2m x 4n), warp 64x32, 3-stage cp.async pipeline.
// Inputs tf32-prerounded.
// ============================================================================
__global__ void __launch_bounds__(256, 2) gemm_mma(
    const float* __restrict__ A, const float* __restrict__ Bm, float* __restrict__ C,
    int M, int N, int K, int lda, int ldb, int ldc,
    float alpha, int rnd)
{
    constexpr int TA = 128*32, SF = 2*TA;
    extern __shared__ float sm[];
    const int tid = threadIdx.x, wid = tid >> 5, lane = tid & 31;
    const int g = lane >> 2, t = lane & 3;
    const int row0 = blockIdx.y * 128, col0 = blockIdx.x * 128;
    const int m0w = (wid >> 2) * 64, n0w = (wid & 3) * 32;
    const int KT = K >> 5;
    const float* Ab = A  + (size_t)row0 * lda;
    const float* Bb = Bm + (size_t)col0 * ldb;

    auto load_stage = [&](int s, int k0) {
        #pragma unroll
        for (int r = 0; r < 4; r++) {
            int id = tid + r*256, row = id >> 3, ch = id & 7, chp = ch ^ (row & 7);
            CPA16(smem_u32(sm + s*SF + row*32 + chp*4), Ab + (size_t)row*lda + k0 + ch*4);
        }
        #pragma unroll
        for (int r = 0; r < 4; r++) {
            int id = tid + r*256, row = id >> 3, ch = id & 7, chp = ch ^ (row & 7);
            CPA16(smem_u32(sm + s*SF + TA + row*32 + chp*4), Bb + (size_t)row*ldb + k0 + ch*4);
        }
    };

    #pragma unroll
    for (int s = 0; s < NSTAGE-1; s++) {
        if (s < KT) load_stage(s, s*KTILE);
        CPA_COMMIT();
    }
    float acc[4][4][4] = {};
    for (int kt = 0; kt < KT; kt++) {
        CPA_WAIT1();
        __syncthreads();
        const int pf = kt + NSTAGE - 1;
        if (pf < KT) load_stage(pf % NSTAGE, pf*KTILE);
        CPA_COMMIT();
        const float* As = sm + (kt % NSTAGE) * SF;
        const float* Bs = As + TA;
        #pragma unroll
        for (int h = 0; h < 2; h++) {
            float4 av[4][2];
            #pragma unroll
            for (int mi = 0; mi < 4; mi++) {
                const int rlo = m0w + mi*16 + g, rhi = rlo + 8;
                av[mi][0] = *(const float4*)(As + rlo*32 + ((2*t+h) ^ (rlo & 7))*4);
                av[mi][1] = *(const float4*)(As + rhi*32 + ((2*t+h) ^ (rhi & 7))*4);
            }
            #pragma unroll
            for (int nj = 0; nj < 4; nj++) {
                const int rb = n0w + nj*8 + g;
                float4 bv = *(const float4*)(Bs + rb*32 + ((2*t+h) ^ (rb & 7))*4);
                #pragma unroll
                for (int mi = 0; mi < 4; mi++) {
                    mma8(acc[mi][nj], av[mi][0].x, av[mi][1].x, av[mi][0].y, av[mi][1].y, bv.x, bv.y);
                    mma8(acc[mi][nj], av[mi][0].z, av[mi][1].z, av[mi][0].w, av[mi][1].w, bv.z, bv.w);
                }
            }
        }
    }
    #pragma unroll
    for (int mi = 0; mi < 4; mi++) {
        const int r = row0 + m0w + mi*16 + g;
        #pragma unroll
        for (int nj = 0; nj < 4; nj++) {
            const int c = col0 + n0w + nj*8 + 2*t;
            float2 v0, v1;
            v0.x = alpha*acc[mi][nj][0]; v0.y = alpha*acc[mi][nj][1];
            v1.x = alpha*acc[mi][nj][2]; v1.y = alpha*acc[mi][nj][3];
            if (rnd) { v0.x=f2tf(v0.x); v0.y=f2tf(v0.y); v1.x=f2tf(v1.x); v1.y=f2tf(v1.y); }
            *(float2*)(C + (size_t)r     * ldc + c) = v0;
            *(float2*)(C + (size_t)(r+8) * ldc + c) = v1;
        }
    }
}

// ============================================================================
// Flash attention (tf32): per CTA, 128 q rows; loop over 16 kv tiles of 128.
// S = q k^T * alpha -> online softmax -> O += P @ Vc (32 cols).  d_s never exists.
// Warp tile for S: 16 rows x 128 cols (row stats warp-local via quad shuffles).
// smem: 3 stages x (q 128x32 + k 128x32) + Ps 128x128 + Vc 32x128 = 176KB.
// ============================================================================
#define FSTG   8192
#define FSM_PS (3*FSTG)
#define FSM_VC (FSM_PS + 16384)
#define FSM_BYTES ((FSM_VC + 4096)*4)

__global__ void __launch_bounds__(256) k_flash(
    const float* __restrict__ qkv, const float* __restrict__ vTc, float* __restrict__ O)
{
    extern __shared__ float sm[];
    const int tid = threadIdx.x, wid = tid >> 5, lane = tid & 31;
    const int g = lane >> 2, t = lane & 3;
    const int b = blockIdx.y, q0 = blockIdx.x * 128;
    const float* Ab = qkv + (size_t)(b*TT + q0) * NQKV;
    float* Ps = sm + FSM_PS;
    float* Vc = sm + FSM_VC;
    const float alpha = 0.044194173824159216f;

    float Oacc[4][4] = {};
    float m0 = -1e30f, m1 = -1e30f, l0 = 0.f, l1 = 0.f;
    const int prow0 = wid*16 + g, prow1 = prow0 + 8;
    const int vrow = tid >> 3, vch = tid & 7, vchp = vch ^ (vrow & 7);

    for (int kv = 0; kv < TT; kv += 128) {
        const float* Bb = qkv + (size_t)(b*TT + kv) * NQKV + 512;

        // Vc loads for this kv tile (joins first commit group)
        #pragma unroll
        for (int sub = 0; sub < 4; sub++)
            CPA16(smem_u32(Vc + sub*1024 + vrow*32 + vchp*4),
                  vTc + ((size_t)b*32 + vrow)*TT + kv + sub*32 + vch*4);

        auto load_stage = [&](int s, int k0) {
            #pragma unroll
            for (int r = 0; r < 4; r++) {
                int id = tid + r*256, row = id >> 3, ch = id & 7, chp = ch ^ (row & 7);
                CPA16(smem_u32(sm + s*FSTG + row*32 + chp*4), Ab + (size_t)row*NQKV + k0 + ch*4);
            }
            #pragma unroll
            for (int r = 0; r < 4; r++) {
                int id = tid + r*256, row = id >> 3, ch = id & 7, chp = ch ^ (row & 7);
                CPA16(smem_u32(sm + s*FSTG + 4096 + row*32 + chp*4), Bb + (size_t)row*NQKV + k0 + ch*4);
            }
        };

        float Sacc[16][4];
        #pragma unroll
        for (int nj = 0; nj < 16; nj++)
            #pragma unroll
            for (int i = 0; i < 4; i++) Sacc[nj][i] = 0.f;

        // ---- S = q k^T mainloop (K = 512) ----
        load_stage(0, 0);  CPA_COMMIT();
        load_stage(1, 32); CPA_COMMIT();
        for (int kt = 0; kt < 16; kt++) {
            CPA_WAIT1();
            __syncthreads();
            const int pf = kt + 2;
            if (pf < 16) load_stage(pf % 3, pf*32);
            CPA_COMMIT();
            const float* As = sm + (kt % 3) * FSTG;
            const float* Bs = As + 4096;
            #pragma unroll
            for (int h = 0; h < 2; h++) {
                const int rlo = prow0, rhi = prow1;
                float4 a0 = *(const float4*)(As + rlo*32 + ((2*t+h) ^ (rlo & 7))*4);
                float4 a1 = *(const float4*)(As + rhi*32 + ((2*t+h) ^ (rhi & 7))*4);
                #pragma unroll
                for (int nj = 0; nj < 16; nj++) {
                    const int rb = nj*8 + g;
                    float4 bv = *(const float4*)(Bs + rb*32 + ((2*t+h) ^ (rb & 7))*4);
                    mma8(Sacc[nj], a0.x, a1.x, a0.y, a1.y, bv.x, bv.y);
                    mma8(Sacc[nj], a0.z, a1.z, a0.w, a1.w, bv.z, bv.w);
                }
            }
        }

        // ---- online softmax (warp-local rows) ----
        float rm0 = -1e30f, rm1 = -1e30f;
        #pragma unroll
        for (int nj = 0; nj < 16; nj++) {
            Sacc[nj][0] *= alpha; Sacc[nj][1] *= alpha;
            Sacc[nj][2] *= alpha; Sacc[nj][3] *= alpha;
            rm0 = fmaxf(rm0, fmaxf(Sacc[nj][0], Sacc[nj][1]));
            rm1 = fmaxf(rm1, fmaxf(Sacc[nj][2], Sacc[nj][3]));
        }
        rm0 = fmaxf(rm0, __shfl_xor_sync(0xffffffffu, rm0, 1));
        rm0 = fmaxf(rm0, __shfl_xor_sync(0xffffffffu, rm0, 2));
        rm1 = fmaxf(rm1, __shfl_xor_sync(0xffffffffu, rm1, 1));
        rm1 = fmaxf(rm1, __shfl_xor_sync(0xffffffffu, rm1, 2));
        const float mn0 = fmaxf(m0, rm0), mn1 = fmaxf(m1, rm1);
        const float f0 = __expf(m0 - mn0), f1 = __expf(m1 - mn1);
        float s0 = 0.f, s1 = 0.f;
        #pragma unroll
        for (int nj = 0; nj < 16; nj++) {
            float p0 = f2tf(__expf(Sacc[nj][0] - mn0));
            float p1 = f2tf(__expf(Sacc[nj][1] - mn0));
            float p2 = f2tf(__expf(Sacc[nj][2] - mn1));
            float p3 = f2tf(__expf(Sacc[nj][3] - mn1));
            s0 += p0 + p1; s1 += p2 + p3;
            const int sub = nj >> 2, cs = (nj & 3)*8 + 2*t;
            const int ch = cs >> 2, off = cs & 3;
            *(float2*)(Ps + sub*4096 + prow0*32 + (ch ^ (prow0 & 7))*4 + off) = make_float2(p0, p1);
            *(float2*)(Ps + sub*4096 + prow1*32 + (ch ^ (prow1 & 7))*4 + off) = make_float2(p2, p3);
        }
        s0 += __shfl_xor_sync(0xffffffffu, s0, 1);
        s0 += __shfl_xor_sync(0xffffffffu, s0, 2);
        s1 += __shfl_xor_sync(0xffffffffu, s1, 1);
        s1 += __shfl_xor_sync(0xffffffffu, s1, 2);
        l0 = l0*f0 + s0; l1 = l1*f1 + s1;
        m0 = mn0; m1 = mn1;
        #pragma unroll
        for (int nj = 0; nj < 4; nj++) {
            Oacc[nj][0] *= f0; Oacc[nj][1] *= f0;
            Oacc[nj][2] *= f1; Oacc[nj][3] *= f1;
        }

        CPA_WAIT0();          // Vc of this tile fully arrived
        __syncthreads();

        // ---- O += P @ Vc ----
        #pragma unroll
        for (int sub = 0; sub < 4; sub++) {
            const float* As2 = Ps + sub*4096;
            const float* Bs2 = Vc + sub*1024;
            #pragma unroll
            for (int h = 0; h < 2; h++) {
                float4 a0 = *(const float4*)(As2 + prow0*32 + ((2*t+h) ^ (prow0 & 7))*4);
                float4 a1 = *(const float4*)(As2 + prow1*32 + ((2*t+h) ^ (prow1 & 7))*4);
                #pragma unroll
                for (int nj = 0; nj < 4; nj++) {
                    const int rb = nj*8 + g;
                    float4 bv = *(const float4*)(Bs2 + rb*32 + ((2*t+h) ^ (rb & 7))*4);
                    mma8(Oacc[nj], a0.x, a1.x, a0.y, a1.y, bv.x, bv.y);
                    mma8(Oacc[nj], a0.z, a1.z, a0.w, a1.w, bv.z, bv.w);
                }
            }
        }
        __syncthreads();      // protect Ps/Vc/stages before next kv tile
    }

    const float i0 = 1.f / l0, i1 = 1.f / l1;
    const int r = q0 + prow0;
    #pragma unroll
    for (int nj = 0; nj < 4; nj++) {
        const int c = nj*8 + 2*t;
        *(float2*)(O + (size_t)(b*TT + r)    *32 + c) = make_float2(Oacc[nj][0]*i0, Oacc[nj][1]*i0);
        *(float2*)(O + (size_t)(b*TT + r + 8)*32 + c) = make_float2(Oacc[nj][2]*i1, Oacc[nj][3]*i1);
    }
}

// ============================================================================
// Fused FFN GEMM: d_f[BTN,512] = (relu(f8 @ w1^T)) @ w2^T, h1 never materialized.
// A-tiles (h1[128x32]) computed per k-tile via a K=32(8-real) sub-MMA from
// SMEM-resident F8 tile and a pipelined w1 slice; B = w2r via cp.async.
// ============================================================================
#define GF_STG 5120                      // w2 tile 4096 + w1 slice 1024
#define GF_ASM (3*GF_STG)
#define GF_F8  (GF_ASM + 2*4096)
#define GF_BYTES ((GF_F8 + 4096)*4)      // 110592 B

__global__ void __launch_bounds__(256, 2) gemm_ffn(
    const float* __restrict__ w2r, const float* __restrict__ f8,
    const float* __restrict__ w1p, float* __restrict__ C)
{
    extern __shared__ float sm[];
    const int tid = threadIdx.x, wid = tid >> 5, lane = tid & 31;
    const int g = lane >> 2, t = lane & 3;
    const int row0 = blockIdx.y * 128, col0 = blockIdx.x * 128;
    const int m0w = (wid >> 2) * 64, n0w = (wid & 3) * 32;
    float* Asm = sm + GF_ASM;
    float* F8s = sm + GF_F8;

    // F8 tile [128x32] swizzled (once)
    #pragma unroll
    for (int r = 0; r < 4; r++) {
        int id = tid + r*256, row = id >> 3, ch = id & 7, chp = ch ^ (row & 7);
        *(float4*)(F8s + row*32 + chp*4) = *(const float4*)(f8 + (size_t)(row0+row)*32 + ch*4);
    }
    __syncthreads();

    const float* Bb = w2r + (size_t)col0 * FFND;
    auto load_stage = [&](int s, int k0) {
        #pragma unroll
        for (int r = 0; r < 4; r++) {
            int id = tid + r*256, row = id >> 3, ch = id & 7, chp = ch ^ (row & 7);
            CPA16(smem_u32(sm + s*GF_STG + row*32 + chp*4), Bb + (size_t)row*FFND + k0 + ch*4);
        }
        {   // w1 slice [32 x 32(8 real)]
            int row = tid >> 3, ch = tid & 7, chp = ch ^ (row & 7);
            CPA16(smem_u32(sm + s*GF_STG + 4096 + row*32 + chp*4), w1p + (size_t)(k0+row)*32 + ch*4);
        }
    };

    load_stage(0, 0);  CPA_COMMIT();
    load_stage(1, 32); CPA_COMMIT();
    float acc[4][4][4] = {};
    const int irow0 = wid*16 + g, irow1 = irow0 + 8;

    for (int kt = 0; kt < 64; kt++) {
        CPA_WAIT1();
        __syncthreads();

        // ---- inner: compute A tile rows [16*wid, 16*wid+16) ----
        {
            float fac[4][4] = {};
            const float* W1s = sm + (kt % 3) * GF_STG + 4096;
            #pragma unroll
            for (int h = 0; h < 2; h++) {
                float4 a0 = *(const float4*)(F8s + irow0*32 + ((2*t+h) ^ (irow0 & 7))*4);
                float4 a1 = *(const float4*)(F8s + irow1*32 + ((2*t+h) ^ (irow1 & 7))*4);
                #pragma unroll
                for (int nj = 0; nj < 4; nj++) {
                    const int rb = nj*8 + g;
                    float4 bv = *(const float4*)(W1s + rb*32 + ((2*t+h) ^ (rb & 7))*4);
                    mma8(fac[nj], a0.x, a1.x, a0.y, a1.y, bv.x, bv.y);
                    mma8(fac[nj], a0.z, a1.z, a0.w, a1.w, bv.z, bv.w);
                }
            }
            float* Ad = Asm + (kt & 1) * 4096;
            #pragma unroll
            for (int nj = 0; nj < 4; nj++) {
                const int cs = nj*8 + 2*t, ch = cs >> 2, off = cs & 3;
                *(float2*)(Ad + irow0*32 + (ch ^ (irow0 & 7))*4 + off) =
                    make_float2(f2tf(fmaxf(fac[nj][0], 0.f)), f2tf(fmaxf(fac[nj][1], 0.f)));
                *(float2*)(Ad + irow1*32 + (ch ^ (irow1 & 7))*4 + off) =
                    make_float2(f2tf(fmaxf(fac[nj][2], 0.f)), f2tf(fmaxf(fac[nj][3], 0.f)));
            }
        }
        __syncthreads();

        const int pf = kt + 2;
        if (pf < 64) load_stage(pf % 3, pf*32);
        CPA_COMMIT();

        // ---- outer mma ----
        const float* As = Asm + (kt & 1) * 4096;
        const float* Bs = sm + (kt % 3) * GF_STG;
        #pragma unroll
        for (int h = 0; h < 2; h++) {
            float4 av[4][2];
            #pragma unroll
            for (int mi = 0; mi < 4; mi++) {
                const int rlo = m0w + mi*16 + g, rhi = rlo + 8;
                av[mi][0] = *(const float4*)(As + rlo*32 + ((2*t+h) ^ (rlo & 7))*4);
                av[mi][1] = *(const float4*)(As + rhi*32 + ((2*t+h) ^ (rhi & 7))*4);
            }
            #pragma unroll
            for (int nj = 0; nj < 4; nj++) {
                const int rb = n0w + nj*8 + g;
                float4 bv = *(const float4*)(Bs + rb*32 + ((2*t+h) ^ (rb & 7))*4);
                #pragma unroll
                for (int mi = 0; mi < 4; mi++) {
                    mma8(acc[mi][nj], av[mi][0].x, av[mi][1].x, av[mi][0].y, av[mi][1].y, bv.x, bv.y);
                    mma8(acc[mi][nj], av[mi][0].z, av[mi][1].z, av[mi][0].w, av[mi][1].w, bv.z, bv.w);
                }
            }
        }
    }
    #pragma unroll
    for (int mi = 0; mi < 4; mi++) {
        const int r = row0 + m0w + mi*16 + g;
        #pragma unroll
        for (int nj = 0; nj < 4; nj++) {
            const int c = col0 + n0w + nj*8 + 2*t;
            *(float2*)(C + (size_t)r     * EE + c) = make_float2(acc[mi][nj][0], acc[mi][nj][1]);
            *(float2*)(C + (size_t)(r+8) * EE + c) = make_float2(acc[mi][nj][2], acc[mi][nj][3]);
        }
    }
}

// ============================================================================
// Parameter-only circuit sims -> closed-form (A,B): qout = A cos(u) + B sin(u)
// ============================================================================
__global__ void k_circuits(const float* __restrict__ hp, const float* __restrict__ fp)
{
    __shared__ float fpsi[256];
    const int t = threadIdx.x;
    if (t < HH) {
        float psi[16];
        #pragma unroll
        for (int i = 0; i < 16; i++) psi[i] = 0.f;
        psi[0] = 1.f;
        for (int l = 0; l < NLAY; l++) {
            for (int q = 0; q < NQH; q++) {
                float th = 0.5f * hp[t*NLAY*NQH + l*NQH + q];
                float c = cosf(th), s = sinf(th);
                int m = 1 << (NQH-1-q);
                for (int i = 0; i < 16; i++)
                    if (!(i & m)) {
                        float a0 = psi[i], a1 = psi[i|m];
                        psi[i] = c*a0 - s*a1; psi[i|m] = s*a0 + c*a1;
                    }
            }
            for (int q = 0; q < NQH; q++) {
                int cm = 1 << (NQH-1-q), tm = 1 << (NQH-1-((q+1)%NQH));
                for (int i = 0; i < 16; i++)
                    if ((i & cm) && !(i & tm)) {
                        float tmp = psi[i]; psi[i] = psi[i|tm]; psi[i|tm] = tmp;
                    }
            }
        }
        for (int q = 0; q < NQH; q++) {
            int m = 1 << (NQH-1-q);
            float z = 0.f, xe = 0.f;
            for (int i = 0; i < 16; i++) {
                z  += ((i & m) ? -1.f : 1.f) * psi[i]*psi[i];
                xe += psi[i]*psi[i^m];
            }
            g_attA[t*NQH+q] = z; g_attB[t*NQH+q] = -xe;
        }
    }
    if (t == HH) {
        for (int i = 0; i < 256; i++) fpsi[i] = 0.f;
        fpsi[0] = 1.f;
        for (int q = 0; q < NQF; q++) {
            float th = 0.5f * fp[q];
            float c = cosf(th), s = sinf(th);
            int m = 1 << (NQF-1-q);
            for (int i = 0; i < 256; i++)
                if (!(i & m)) {
                    float a0 = fpsi[i], a1 = fpsi[i|m];
                    fpsi[i] = c*a0 - s*a1; fpsi[i|m] = s*a0 + c*a1;
                }
        }
        for (int q = 0; q < NQF; q++) {
            int cm = 1 << (NQF-1-q), tm = 1 << (NQF-1-((q+1)%NQF));
            for (int i = 0; i < 256; i++)
                if ((i & cm) && !(i & tm)) {
                    float tmp = fpsi[i]; fpsi[i] = fpsi[i|tm]; fpsi[i|tm] = tmp;
                }
        }
        for (int q = 0; q < NQF; q++) {
            int m = 1 << (NQF-1-q);
            float z = 0.f, xe = 0.f;
            for (int i = 0; i < 256; i++) {
                z  += ((i & m) ? -1.f : 1.f) * fpsi[i]*fpsi[i];
                xe += fpsi[i]*fpsi[i^m];
            }
            g_ffnA[q] = z; g_ffnB[q] = -xe;
        }
    }
}

// ---- elementwise tf32 rounding (float4) ------------------------------------
__global__ void k_round4(const float* __restrict__ in, float* __restrict__ out)
{
    const int i = blockIdx.x*256 + threadIdx.x;
    float4 v = ((const float4*)in)[i];
    v.x = f2tf(v.x); v.y = f2tf(v.y); v.z = f2tf(v.z); v.w = f2tf(v.w);
    ((float4*)out)[i] = v;
}

// ---- build packed+rounded [wq; wk; wv_compact; 0] weight ------------------
__global__ void k_prep_wqkv(const float* __restrict__ wq, const float* __restrict__ wk,
                            const float* __restrict__ wv, float* __restrict__ w)
{
    const int idx = blockIdx.x*256 + threadIdx.x;      // NQKV*EE
    const int n = idx >> 9, k = idx & 511;
    float v;
    if      (n < 512)  v = wq[(size_t)n*EE + k];
    else if (n < 1024) v = wk[(size_t)(n-512)*EE + k];
    else if (n < 1056) { int j = n - 1024; v = wv[(size_t)((j>>2)*HD + (j&3))*EE + k]; }
    else               v = 0.f;
    w[idx] = f2tf(v);
}

// ---- compact V transpose: vTc[b][j][t] = qkv[b*TT+t][1024+j] ---------------
__global__ void k_vtransc()
{
    __shared__ float tile[32][33];
    const int b = blockIdx.z, t0 = blockIdx.x*32;
    const int tx = threadIdx.x, ty = threadIdx.y;          // (32, 8)
    #pragma unroll
    for (int i = 0; i < 32; i += 8)
        tile[ty+i][tx] = d_qkv[(size_t)(b*TT + t0+ty+i)*NQKV + 1024 + tx];
    __syncthreads();
    #pragma unroll
    for (int i = 0; i < 32; i += 8)
        d_vTc[(size_t)b*32*TT + (size_t)(ty+i)*TT + t0+tx] = tile[tx][ty+i];
}

// ---- quantum head map on compact o -----------------------------------------
__global__ void k_qmap(float* __restrict__ q32)
{
    const int idx = blockIdx.x*256 + threadIdx.x;      // BTN*32
    const int j = idx & 31;
    const float u = d_o[idx];
    q32[idx] = f2tf(g_attA[j]*cosf(u) + g_attB[j]*sinf(u));
}

// ---- compact wo ------------------------------------------------------------
__global__ void k_woc(const float* __restrict__ wo, float* __restrict__ woc)
{
    const int idx = blockIdx.x*256 + threadIdx.x;      // EE*32
    const int e = idx >> 5, j = idx & 31;
    woc[idx] = f2tf(wo[(size_t)e*EE + (j>>2)*HD + (j&3)]);
}

// ---- pad w1 [2048,8] -> [2048,32], rounded ---------------------------------
__global__ void k_w1pad(const float* __restrict__ w1, float* __restrict__ w1p)
{
    const int idx = blockIdx.x*256 + threadIdx.x;      // FFND*32
    const int f = idx >> 5, j = idx & 31;
    w1p[idx] = (j < 8) ? f2tf(w1[f*8 + j]) : 0.f;
}

// ---- FFN quantum map (padded to 32), rounded -------------------------------
__global__ void k_f8(float* __restrict__ f8p)
{
    const int idx = blockIdx.x*256 + threadIdx.x;      // BTN*32
    const int bt = idx >> 5, j = idx & 31;
    float r = 0.f;
    if (j < 8) {
        const float u = d_x1[(size_t)bt*EE + j];
        r = f2tf(g_ffnA[j]*cosf(u) + g_ffnB[j]*sinf(u));
    }
    f8p[idx] = r;
}

// ---- generic residual LayerNorm: out = LN(a + c) ---------------------------
__global__ void __launch_bounds__(256) k_ln(
    const float* __restrict__ a, const float* __restrict__ c,
    const float* __restrict__ g, const float* __restrict__ bb, float* __restrict__ out)
{
    const size_t bt = blockIdx.x;
    __shared__ float red[256];
    const int t = threadIdx.x;
    float v0 = a[bt*EE + t]       + c[bt*EE + t];
    float v1 = a[bt*EE + t + 256] + c[bt*EE + t + 256];
    red[t] = v0 + v1; __syncthreads();
    for (int st = 128; st > 0; st >>= 1) { if (t < st) red[t] += red[t+st]; __syncthreads(); }
    const float mean = red[0] * (1.f/EE);
    __syncthreads();
    float d0 = v0 - mean, d1 = v1 - mean;
    red[t] = d0*d0 + d1*d1; __syncthreads();
    for (int st = 128; st > 0; st >>= 1) { if (t < st) red[t] += red[t+st]; __syncthreads(); }
    const float rstd = rsqrtf(red[0]*(1.f/EE) + 1e-5f);
    out[bt*EE + t]       = d0*rstd*g[t]     + bb[t];
    out[bt*EE + t + 256] = d1*rstd*g[t+256] + bb[t+256];
}

// ============================================================================
extern "C" void kernel_launch(void* const* d_in, const int* in_sizes, int n_in,
                              void* d_out, int out_size)
{
    const float* x  = (const float*)d_in[0];
    const float* wq = (const float*)d_in[1];
    const float* wk = (const float*)d_in[2];
    const float* wv = (const float*)d_in[3];
    const float* wo = (const float*)d_in[4];
    const float* hp = (const float*)d_in[5];
    const float* fp = (const float*)d_in[6];
    const float* w1 = (const float*)d_in[7];
    const float* w2 = (const float*)d_in[8];
    const float* g1 = (const float*)d_in[9];
    const float* b1 = (const float*)d_in[10];
    const float* g2 = (const float*)d_in[11];
    const float* b2 = (const float*)d_in[12];
    float* out = (float*)d_out;

    const int SMG = NSTAGE*2*128*32*4;   // 98304 for gemm_mma
    cudaFuncSetAttribute(gemm_mma, cudaFuncAttributeMaxDynamicSharedMemorySize, SMG);
    cudaFuncSetAttribute(k_flash,  cudaFuncAttributeMaxDynamicSharedMemorySize, FSM_BYTES);
    cudaFuncSetAttribute(gemm_ffn, cudaFuncAttributeMaxDynamicSharedMemorySize, GF_BYTES);

    float *pxr, *pwqkv, *pqkv, *pvTc, *po, *pq32, *pwoc, *patt, *px1, *pf8, *pw1p, *pw2r, *pf;
    cudaGetSymbolAddress((void**)&pxr,   d_xr);
    cudaGetSymbolAddress((void**)&pwqkv, d_wqkv);
    cudaGetSymbolAddress((void**)&pqkv,  d_qkv);
    cudaGetSymbolAddress((void**)&pvTc,  d_vTc);
    cudaGetSymbolAddress((void**)&po,    d_o);
    cudaGetSymbolAddress((void**)&pq32,  d_q32);
    cudaGetSymbolAddress((void**)&pwoc,  d_woc);
    cudaGetSymbolAddress((void**)&patt,  d_att);
    cudaGetSymbolAddress((void**)&px1,   d_x1);
    cudaGetSymbolAddress((void**)&pf8,   d_f8);
    cudaGetSymbolAddress((void**)&pw1p,  d_w1p);
    cudaGetSymbolAddress((void**)&pw2r,  d_w2r);
    cudaGetSymbolAddress((void**)&pf,    d_f);

    // ---- prep ----
    k_circuits<<<1, 32>>>(hp, fp);
    k_round4<<<(BTN*EE/4)/256, 256>>>(x,  pxr);
    k_round4<<<(EE*FFND/4)/256, 256>>>(w2, pw2r);
    k_prep_wqkv<<<(NQKV*EE)/256, 256>>>(wq, wk, wv, pwqkv);
    k_woc<<<(EE*32)/256, 256>>>(wo, pwoc);
    k_w1pad<<<(FFND*32)/256, 256>>>(w1, pw1p);

    // ---- fused QKV projection (q | k | v_compact), rounded output ----
    gemm_mma<<<dim3(NQKV/128, BTN/128, 1), 256, SMG>>>(
        pxr, pwqkv, pqkv, BTN, NQKV, EE, EE, EE, NQKV, 1.f, 1);

    k_vtransc<<<dim3(TT/32, 1, BB), dim3(32, 8)>>>();

    // ---- flash attention: scores+softmax+attnV fused -> d_o [BTN,32] ----
    k_flash<<<dim3(TT/128, BB, 1), 256, FSM_BYTES>>>(pqkv, pvTc, po);

    // ---- quantum head map + wo projection + LN1 ----
    k_qmap<<<(BTN*32)/256, 256>>>(pq32);
    gemm_mma<<<dim3(EE/128, BTN/128, 1), 256, SMG>>>(
        pq32, pwoc, patt, BTN, EE, 32, 32, 32, EE, 1.f, 0);
    k_ln<<<BTN, 256>>>(x, patt, g1, b1, px1);

    // ---- FFN: quantum map -> fused (w1+relu+w2) ----
    k_f8<<<(BTN*32)/256, 256>>>(pf8);
    gemm_ffn<<<dim3(EE/128, BTN/128, 1), 256, GF_BYTES>>>(pw2r, pf8, pw1p, pf);

    k_ln<<<BTN, 256>>>(px1, pf, g2, b2, out);
}

// round 15
// speedup vs baseline: 1.8822x; 1.8822x over previous
#include <cuda_runtime.h>
#include <cuda_fp16.h>
#include <cstdint>
#include <math.h>

#define BB   8
#define TT   2048
#define EE   512
#define HH   8
#define HD   64
#define NQH  4
#define NLAY 2
#define NQF  8
#define FFND 2048
#define BTN  (BB*TT)
#define NQKV 1152              // 512 q + 512 k + 32 v_compact + 96 pad

#define NSTAGE 4

// ---- scratch (static device globals; no allocation allowed) ----
static __device__ __align__(16) __half d_xh  [(size_t)BTN*EE];
static __device__ __align__(16) __half d_wqkv[(size_t)NQKV*EE];
static __device__ __align__(16) __half d_qkv [(size_t)BTN*NQKV];
static __device__ __align__(16) __half d_vTc [(size_t)BB*32*TT];
static __device__ __align__(16) __half d_s   [(size_t)BB*TT*TT];
static __device__ __align__(16) __half d_o   [(size_t)BTN*32];
static __device__ __align__(16) __half d_q32 [(size_t)BTN*32];
static __device__ __align__(16) __half d_woc [(size_t)EE*32];
static __device__ __align__(16) __half d_f8  [(size_t)BTN*32];
static __device__ __align__(16) __half d_w1p [(size_t)FFND*32];
static __device__ __align__(16) __half d_w2h [(size_t)EE*FFND];
static __device__ __align__(16) __half d_h1  [(size_t)BTN*FFND];
static __device__ float d_att [(size_t)BTN*EE];
static __device__ float d_x1  [(size_t)BTN*EE];
static __device__ float d_f   [(size_t)BTN*EE];
static __device__ float g_attA[32], g_attB[32], g_ffnA[8], g_ffnB[8];

// ============================ helpers =======================================
__device__ __forceinline__ uint32_t smem_u32(const void* p) {
    uint32_t a;
    asm("{ .reg .u64 t; cvta.to.shared.u64 t, %1; cvt.u32.u64 %0, t; }" : "=r"(a) : "l"(p));
    return a;
}
__device__ __forceinline__ void ldsm4(uint32_t& r0, uint32_t& r1, uint32_t& r2, uint32_t& r3,
                                      uint32_t addr) {
    asm volatile("ldmatrix.sync.aligned.m8n8.x4.shared.b16 {%0,%1,%2,%3}, [%4];"
                 : "=r"(r0), "=r"(r1), "=r"(r2), "=r"(r3) : "r"(addr));
}
__device__ __forceinline__ void mmah(float* d,
    uint32_t a0, uint32_t a1, uint32_t a2, uint32_t a3, uint32_t b0, uint32_t b1)
{
    asm volatile(
        "mma.sync.aligned.m16n8k16.row.col.f32.f16.f16.f32 "
        "{%0,%1,%2,%3}, {%4,%5,%6,%7}, {%8,%9}, {%0,%1,%2,%3};"
        : "+f"(d[0]), "+f"(d[1]), "+f"(d[2]), "+f"(d[3])
        : "r"(a0), "r"(a1), "r"(a2), "r"(a3), "r"(b0), "r"(b1));
}
#define CPA16(dst, src) \
    asm volatile("cp.async.cg.shared.global [%0], [%1], 16;" :: "r"(dst), "l"(src) : "memory")
#define CPA_COMMIT() asm volatile("cp.async.commit_group;" ::: "memory")
#define CPA_WAITN()  asm volatile("cp.async.wait_group %0;" :: "n"(NSTAGE-2) : "memory")

// ============================================================================
// fp16 mma.sync NT GEMM: C[M,N] = act(alpha * A[M,K] * B[N,K]^T), fp32 accum.
// CTA 128 x BN (BN = 128 or 32), 8 warps, 4-stage cp.async pipeline, k-tile 32.
// SMEM rows = 32 halves (64B), 4x16B chunks, swizzle c ^ ((row>>1)&3):
// conflict-free for cp.async stores and ldmatrix 8-row phases.
// Fragments via ldmatrix.m8n8.x4 (A: per mi/kstep; B: per nj covers both ksteps).
// M % 128 == 0, N % BN == 0, K % 32 == 0.
// ============================================================================
template<int BN, bool HOUT>
__global__ void __launch_bounds__(256, 2) gemm_h(
    const __half* __restrict__ A, const __half* __restrict__ Bm, void* __restrict__ Cv,
    int M, int N, int K, int lda, int ldb, int ldc,
    float alpha, int relu, size_t sA, size_t sB, size_t sC)
{
    constexpr int NWN = BN/32;
    constexpr int NWM = 8/NWN;
    constexpr int MI  = (128/NWM)/16;
    constexpr int TAB = 128*64;          // A tile bytes per stage
    constexpr int TBB = BN*64;           // B tile bytes per stage
    constexpr int SB  = TAB + TBB;

    extern __shared__ char smc[];
    A  += (size_t)blockIdx.z * sA;
    Bm += (size_t)blockIdx.z * sB;

    const int tid = threadIdx.x, wid = tid >> 5, lane = tid & 31;
    const int g = lane >> 2, t = lane & 3;
    const int r8 = lane & 7, q = lane >> 3;
    const int row0 = blockIdx.y * 128, col0 = blockIdx.x * BN;
    const int m0w = (wid / NWN) * (MI*16);
    const int n0w = (wid % NWN) * 32;
    const int KT = K >> 5;
    const __half* Ab = A  + (size_t)row0 * lda;
    const __half* Bb = Bm + (size_t)col0 * ldb;
    const uint32_t sbase = smem_u32(smc);

    auto load_stage = [&](int s, int k0) {
        const uint32_t ab = sbase + s*SB;
        #pragma unroll
        for (int rr = 0; rr < 2; rr++) {                 // A: 512 chunks
            int id = tid + rr*256;
            int row = id >> 2, c = id & 3;
            CPA16(ab + row*64 + ((c ^ ((row>>1)&3)) << 4),
                  Ab + (size_t)row*lda + k0 + c*8);
        }
        const uint32_t bbs = ab + TAB;
        constexpr int BCH = BN*4;
        #pragma unroll
        for (int rr = 0; rr < (BCH+255)/256; rr++) {     // B: BN*4 chunks
            int id = tid + rr*256;
            if (BCH >= 256 || id < BCH) {
                int row = id >> 2, c = id & 3;
                CPA16(bbs + row*64 + ((c ^ ((row>>1)&3)) << 4),
                      Bb + (size_t)row*ldb + k0 + c*8);
            }
        }
    };

    #pragma unroll
    for (int s = 0; s < NSTAGE-1; s++) {
        if (s < KT) load_stage(s, s*32);
        CPA_COMMIT();
    }

    float acc[MI][4][4] = {};
    for (int kt = 0; kt < KT; kt++) {
        CPA_WAITN();
        __syncthreads();
        const int pf = kt + NSTAGE - 1;
        if (pf < KT) load_stage(pf % NSTAGE, pf*32);
        CPA_COMMIT();

        const uint32_t ab = sbase + (kt % NSTAGE) * SB;
        const uint32_t bbs = ab + TAB;

        uint32_t bf[4][4];
        #pragma unroll
        for (int nj = 0; nj < 4; nj++) {
            const int brow = n0w + nj*8 + r8;
            ldsm4(bf[nj][0], bf[nj][1], bf[nj][2], bf[nj][3],
                  bbs + brow*64 + ((q ^ ((brow>>1)&3)) << 4));
        }
        #pragma unroll
        for (int ks = 0; ks < 2; ks++) {
            #pragma unroll
            for (int mi = 0; mi < MI; mi++) {
                const int arow = m0w + mi*16 + r8 + (q & 1)*8;
                const int ac = (q >> 1) + 2*ks;
                uint32_t a0, a1, a2, a3;
                ldsm4(a0, a1, a2, a3, ab + arow*64 + ((ac ^ ((arow>>1)&3)) << 4));
                #pragma unroll
                for (int nj = 0; nj < 4; nj++)
                    mmah(acc[mi][nj], a0, a1, a2, a3, bf[nj][2*ks], bf[nj][2*ks+1]);
            }
        }
    }

    // ---- epilogue ----
    #pragma unroll
    for (int mi = 0; mi < MI; mi++) {
        const int r = row0 + m0w + mi*16 + g;
        #pragma unroll
        for (int nj = 0; nj < 4; nj++) {
            const int c = col0 + n0w + nj*8 + 2*t;
            float v0 = alpha*acc[mi][nj][0], v1 = alpha*acc[mi][nj][1];
            float v2 = alpha*acc[mi][nj][2], v3 = alpha*acc[mi][nj][3];
            if (relu) {
                v0 = fmaxf(v0, 0.f); v1 = fmaxf(v1, 0.f);
                v2 = fmaxf(v2, 0.f); v3 = fmaxf(v3, 0.f);
            }
            if (HOUT) {
                __half* C = (__half*)Cv + (size_t)blockIdx.z * sC;
                *(__half2*)(C + (size_t)r     * ldc + c) = __floats2half2_rn(v0, v1);
                *(__half2*)(C + (size_t)(r+8) * ldc + c) = __floats2half2_rn(v2, v3);
            } else {
                float* C = (float*)Cv + (size_t)blockIdx.z * sC;
                *(float2*)(C + (size_t)r     * ldc + c) = make_float2(v0, v1);
                *(float2*)(C + (size_t)(r+8) * ldc + c) = make_float2(v2, v3);
            }
        }
    }
}

// ============================================================================
// Parameter-only circuit sims -> closed-form (A,B): qout = A cos(u) + B sin(u)
// ============================================================================
__global__ void k_circuits(const float* __restrict__ hp, const float* __restrict__ fp)
{
    __shared__ float fpsi[256];
    const int t = threadIdx.x;
    if (t < HH) {
        float psi[16];
        #pragma unroll
        for (int i = 0; i < 16; i++) psi[i] = 0.f;
        psi[0] = 1.f;
        for (int l = 0; l < NLAY; l++) {
            for (int q = 0; q < NQH; q++) {
                float th = 0.5f * hp[t*NLAY*NQH + l*NQH + q];
                float c = cosf(th), s = sinf(th);
                int m = 1 << (NQH-1-q);
                for (int i = 0; i < 16; i++)
                    if (!(i & m)) {
                        float a0 = psi[i], a1 = psi[i|m];
                        psi[i] = c*a0 - s*a1; psi[i|m] = s*a0 + c*a1;
                    }
            }
            for (int q = 0; q < NQH; q++) {
                int cm = 1 << (NQH-1-q), tm = 1 << (NQH-1-((q+1)%NQH));
                for (int i = 0; i < 16; i++)
                    if ((i & cm) && !(i & tm)) {
                        float tmp = psi[i]; psi[i] = psi[i|tm]; psi[i|tm] = tmp;
                    }
            }
        }
        for (int q = 0; q < NQH; q++) {
            int m = 1 << (NQH-1-q);
            float z = 0.f, xe = 0.f;
            for (int i = 0; i < 16; i++) {
                z  += ((i & m) ? -1.f : 1.f) * psi[i]*psi[i];
                xe += psi[i]*psi[i^m];
            }
            g_attA[t*NQH+q] = z; g_attB[t*NQH+q] = -xe;
        }
    }
    if (t == HH) {
        for (int i = 0; i < 256; i++) fpsi[i] = 0.f;
        fpsi[0] = 1.f;
        for (int q = 0; q < NQF; q++) {
            float th = 0.5f * fp[q];
            float c = cosf(th), s = sinf(th);
            int m = 1 << (NQF-1-q);
            for (int i = 0; i < 256; i++)
                if (!(i & m)) {
                    float a0 = fpsi[i], a1 = fpsi[i|m];
                    fpsi[i] = c*a0 - s*a1; fpsi[i|m] = s*a0 + c*a1;
                }
        }
        for (int q = 0; q < NQF; q++) {
            int cm = 1 << (NQF-1-q), tm = 1 << (NQF-1-((q+1)%NQF));
            for (int i = 0; i < 256; i++)
                if ((i & cm) && !(i & tm)) {
                    float tmp = fpsi[i]; fpsi[i] = fpsi[i|tm]; fpsi[i|tm] = tmp;
                }
        }
        for (int q = 0; q < NQF; q++) {
            int m = 1 << (NQF-1-q);
            float z = 0.f, xe = 0.f;
            for (int i = 0; i < 256; i++) {
                z  += ((i & m) ? -1.f : 1.f) * fpsi[i]*fpsi[i];
                xe += fpsi[i]*fpsi[i^m];
            }
            g_ffnA[q] = z; g_ffnB[q] = -xe;
        }
    }
}

// ---- float -> half conversion (4 elems/thread) -----------------------------
__global__ void k_tohalf4(const float* __restrict__ in, __half* __restrict__ out)
{
    const int i = blockIdx.x*256 + threadIdx.x;
    float4 v = ((const float4*)in)[i];
    ((__half2*)out)[2*i]   = __floats2half2_rn(v.x, v.y);
    ((__half2*)out)[2*i+1] = __floats2half2_rn(v.z, v.w);
}

// ---- build packed half [wq; wk; wv_compact; 0] weight ----------------------
__global__ void k_prep_wqkv(const float* __restrict__ wq, const float* __restrict__ wk,
                            const float* __restrict__ wv, __half* __restrict__ w)
{
    const int idx = blockIdx.x*256 + threadIdx.x;      // NQKV*EE
    const int n = idx >> 9, k = idx & 511;
    float v;
    if      (n < 512)  v = wq[(size_t)n*EE + k];
    else if (n < 1024) v = wk[(size_t)(n-512)*EE + k];
    else if (n < 1056) { int j = n - 1024; v = wv[(size_t)((j>>2)*HD + (j&3))*EE + k]; }
    else               v = 0.f;
    w[idx] = __float2half_rn(v);
}

// ---- compact V transpose: vTc[b][j][t] = qkv[b*TT+t][1024+j] ---------------
__global__ void k_vtransc()
{
    __shared__ float tile[32][33];
    const int b = blockIdx.z, t0 = blockIdx.x*32;
    const int tx = threadIdx.x, ty = threadIdx.y;          // (32, 8)
    #pragma unroll
    for (int i = 0; i < 32; i += 8)
        tile[ty+i][tx] = __half2float(d_qkv[(size_t)(b*TT + t0+ty+i)*NQKV + 1024 + tx]);
    __syncthreads();
    #pragma unroll
    for (int i = 0; i < 32; i += 8)
        d_vTc[(size_t)b*32*TT + (size_t)(ty+i)*TT + t0+tx] = __float2half_rn(tile[tx][ty+i]);
}

// ---- softmax over half rows of 2048 (1 read + 1 write) ---------------------
__global__ void __launch_bounds__(256) k_softmax_h(__half* __restrict__ S)
{
    const size_t row = blockIdx.x;
    uint4* p = (uint4*)(S + row*(size_t)TT);
    const int t = threadIdx.x;
    __shared__ float red[256];
    uint4 v = p[t];
    __half2* hp = (__half2*)&v;
    float2 f[4];
    #pragma unroll
    for (int i = 0; i < 4; i++) f[i] = __half22float2(hp[i]);
    float m = -1e30f;
    #pragma unroll
    for (int i = 0; i < 4; i++) m = fmaxf(m, fmaxf(f[i].x, f[i].y));
    red[t] = m; __syncthreads();
    for (int st = 128; st > 0; st >>= 1) { if (t < st) red[t] = fmaxf(red[t], red[t+st]); __syncthreads(); }
    m = red[0]; __syncthreads();
    float sum = 0.f;
    #pragma unroll
    for (int i = 0; i < 4; i++) {
        f[i].x = __expf(f[i].x - m); f[i].y = __expf(f[i].y - m);
        sum += f[i].x + f[i].y;
    }
    red[t] = sum; __syncthreads();
    for (int st = 128; st > 0; st >>= 1) { if (t < st) red[t] += red[t+st]; __syncthreads(); }
    const float inv = 1.f / red[0];
    #pragma unroll
    for (int i = 0; i < 4; i++)
        hp[i] = __floats2half2_rn(f[i].x*inv, f[i].y*inv);
    p[t] = v;
}

// ---- quantum head map: q32[bt][j] = A_j cos(u) + B_j sin(u) ----------------
__global__ void k_qmap()
{
    const int idx = blockIdx.x*256 + threadIdx.x;      // BTN*32
    const int j = idx & 31;
    const float u = __half2float(d_o[idx]);
    d_q32[idx] = __float2half_rn(g_attA[j]*cosf(u) + g_attB[j]*sinf(u));
}

// ---- compact wo (half) -----------------------------------------------------
__global__ void k_woc(const float* __restrict__ wo)
{
    const int idx = blockIdx.x*256 + threadIdx.x;      // EE*32
    const int e = idx >> 5, j = idx & 31;
    d_woc[idx] = __float2half_rn(wo[(size_t)e*EE + (j>>2)*HD + (j&3)]);
}

// ---- pad w1 [2048,8] -> [2048,32] half -------------------------------------
__global__ void k_w1pad(const float* __restrict__ w1)
{
    const int idx = blockIdx.x*256 + threadIdx.x;      // FFND*32
    const int f = idx >> 5, j = idx & 31;
    d_w1p[idx] = __float2half_rn((j < 8) ? w1[f*8 + j] : 0.f);
}

// ---- FFN quantum map (padded to 32), half ----------------------------------
__global__ void k_f8()
{
    const int idx = blockIdx.x*256 + threadIdx.x;      // BTN*32
    const int bt = idx >> 5, j = idx & 31;
    float r = 0.f;
    if (j < 8) {
        const float u = d_x1[(size_t)bt*EE + j];
        r = g_ffnA[j]*cosf(u) + g_ffnB[j]*sinf(u);
    }
    d_f8[idx] = __float2half_rn(r);
}

// ---- generic residual LayerNorm: out = LN(a + c) ---------------------------
__global__ void __launch_bounds__(256) k_ln(
    const float* __restrict__ a, const float* __restrict__ c,
    const float* __restrict__ g, const float* __restrict__ bb, float* __restrict__ out)
{
    const size_t bt = blockIdx.x;
    __shared__ float red[256];
    const int t = threadIdx.x;
    float v0 = a[bt*EE + t]       + c[bt*EE + t];
    float v1 = a[bt*EE + t + 256] + c[bt*EE + t + 256];
    red[t] = v0 + v1; __syncthreads();
    for (int st = 128; st > 0; st >>= 1) { if (t < st) red[t] += red[t+st]; __syncthreads(); }
    const float mean = red[0] * (1.f/EE);
    __syncthreads();
    float d0 = v0 - mean, d1 = v1 - mean;
    red[t] = d0*d0 + d1*d1; __syncthreads();
    for (int st = 128; st > 0; st >>= 1) { if (t < st) red[t] += red[t+st]; __syncthreads(); }
    const float rstd = rsqrtf(red[0]*(1.f/EE) + 1e-5f);
    out[bt*EE + t]       = d0*rstd*g[t]     + bb[t];
    out[bt*EE + t + 256] = d1*rstd*g[t+256] + bb[t+256];
}

// ============================================================================
extern "C" void kernel_launch(void* const* d_in, const int* in_sizes, int n_in,
                              void* d_out, int out_size)
{
    const float* x  = (const float*)d_in[0];
    const float* wq = (const float*)d_in[1];
    const float* wk = (const float*)d_in[2];
    const float* wv = (const float*)d_in[3];
    const float* wo = (const float*)d_in[4];
    const float* hp = (const float*)d_in[5];
    const float* fp = (const float*)d_in[6];
    const float* w1 = (const float*)d_in[7];
    const float* w2 = (const float*)d_in[8];
    const float* g1 = (const float*)d_in[9];
    const float* b1 = (const float*)d_in[10];
    const float* g2 = (const float*)d_in[11];
    const float* b2 = (const float*)d_in[12];
    float* out = (float*)d_out;

    const int SM128 = NSTAGE*(128+128)*64;   // 65536 B
    const int SM32  = NSTAGE*(128+ 32)*64;   // 40960 B
    cudaFuncSetAttribute((const void*)gemm_h<128,true>,  cudaFuncAttributeMaxDynamicSharedMemorySize, SM128);
    cudaFuncSetAttribute((const void*)gemm_h<128,false>, cudaFuncAttributeMaxDynamicSharedMemorySize, SM128);
    cudaFuncSetAttribute((const void*)gemm_h<32,true>,   cudaFuncAttributeMaxDynamicSharedMemorySize, SM32);

    __half *pxh, *pwqkv, *pqkv, *pvTc, *ps, *po, *pq32, *pwoc, *pf8, *pw1p, *pw2h, *ph1;
    float *patt, *px1, *pf;
    cudaGetSymbolAddress((void**)&pxh,   d_xh);
    cudaGetSymbolAddress((void**)&pwqkv, d_wqkv);
    cudaGetSymbolAddress((void**)&pqkv,  d_qkv);
    cudaGetSymbolAddress((void**)&pvTc,  d_vTc);
    cudaGetSymbolAddress((void**)&ps,    d_s);
    cudaGetSymbolAddress((void**)&po,    d_o);
    cudaGetSymbolAddress((void**)&pq32,  d_q32);
    cudaGetSymbolAddress((void**)&pwoc,  d_woc);
    cudaGetSymbolAddress((void**)&pf8,   d_f8);
    cudaGetSymbolAddress((void**)&pw1p,  d_w1p);
    cudaGetSymbolAddress((void**)&pw2h,  d_w2h);
    cudaGetSymbolAddress((void**)&ph1,   d_h1);
    cudaGetSymbolAddress((void**)&patt,  d_att);
    cudaGetSymbolAddress((void**)&px1,   d_x1);
    cudaGetSymbolAddress((void**)&pf,    d_f);

    // ---- prep: circuit constants + half operands ----
    k_circuits<<<1, 32>>>(hp, fp);
    k_tohalf4<<<(BTN*EE/4)/256, 256>>>(x,  pxh);
    k_tohalf4<<<(EE*FFND/4)/256, 256>>>(w2, pw2h);
    k_prep_wqkv<<<(NQKV*EE)/256, 256>>>(wq, wk, wv, pwqkv);
    k_woc<<<(EE*32)/256, 256>>>(wo);
    k_w1pad<<<(FFND*32)/256, 256>>>(w1);

    // ---- fused QKV projection (q | k | v_compact) -> half ----
    gemm_h<128,true><<<dim3(NQKV/128, BTN/128, 1), 256, SM128>>>(
        pxh, pwqkv, pqkv, BTN, NQKV, EE, EE, EE, NQKV, 1.f, 0, 0, 0, 0);

    k_vtransc<<<dim3(TT/32, 1, BB), dim3(32, 8)>>>();

    // ---- scores = q k^T / sqrt(E) -> half ----
    gemm_h<128,true><<<dim3(TT/128, TT/128, BB), 256, SM128>>>(
        pqkv, pqkv + 512, ps, TT, TT, EE, NQKV, NQKV, TT, 0.044194173824159216f, 0,
        (size_t)TT*NQKV, (size_t)TT*NQKV, (size_t)TT*TT);

    k_softmax_h<<<BTN, 256>>>(ps);

    // ---- o = attn @ v_compact (N = 32) -> half ----
    gemm_h<32,true><<<dim3(1, TT/128, BB), 256, SM32>>>(
        ps, pvTc, po, TT, 32, TT, TT, TT, 32, 1.f, 0,
        (size_t)TT*TT, (size_t)32*TT, (size_t)TT*32);

    // ---- quantum head map + wo projection + LN1 ----
    k_qmap<<<(BTN*32)/256, 256>>>();
    gemm_h<128,false><<<dim3(EE/128, BTN/128, 1), 256, SM128>>>(
        pq32, pwoc, patt, BTN, EE, 32, 32, 32, EE, 1.f, 0, 0, 0, 0);
    k_ln<<<BTN, 256>>>(x, patt, g1, b1, px1);

    // ---- FFN: quantum map -> w1(+relu) half -> w2 ----
    k_f8<<<(BTN*32)/256, 256>>>();
    gemm_h<128,true><<<dim3(FFND/128, BTN/128, 1), 256, SM128>>>(
        pf8, pw1p, ph1, BTN, FFND, 32, 32, 32, FFND, 1.f, 1, 0, 0, 0);
    gemm_h<128,false><<<dim3(EE/128, BTN/128, 1), 256, SM128>>>(
        ph1, pw2h, pf, BTN, EE, FFND, FFND, FFND, EE, 1.f, 0, 0, 0, 0);

    k_ln<<<BTN, 256>>>(px1, pf, g2, b2, out);
}